// round 8
// baseline (speedup 1.0000x reference)
#include <cuda_runtime.h>
#include <cuda_fp16.h>

#define NSEG   8
#define KPTS   768
#define NMAPS  7
#define NPTS   (NSEG * KPTS)        // 6144
#define EPM    (KPTS * KPTS)        // 589824
#define ETOT   (NMAPS * EPM)        // 4128768

#define REPACK_BLOCKS (NMAPS * 1048576 / 4 / 256)   // 7168 (4 pixels/thread)
#define TABLE_BLOCKS  (NPTS / 256)                   // 24
#define APAIRS        (KPTS / 2)                     // 384
#define MAIN_BLOCKS   (NMAPS * APAIRS * 3)           // 8064 (512 edges each)

// Scratch: channel-interleaved PAF in fp16: pixel -> half2(c0, c1), 28 MB
__device__ __half2 g_paf[NMAPS * 1048576];
// Packed per-point records: {x, y, paf.x, paf.y} (fp32 floats bit-cast into .z/.w)
__device__ int4 g_ptA[NPTS];   // endpoint sample as p1 (map seg(i):   x=0 sample == p1)
__device__ int4 g_ptB[NPTS];   // endpoint sample as p2 (map seg(i)-1: x=9 sample == p2)

// Repack (m, c, y, x) fp32 -> (m, y, x) half2(c0,c1); 4 pixels/thread, 16B stores.
// Tail blocks build the exact fp32 endpoint table.
__global__ void prep_kernel(const int* __restrict__ sk, const float* __restrict__ PAF) {
    if (blockIdx.x < REPACK_BLOCKS) {
        int t    = blockIdx.x * 256 + threadIdx.x;     // one t per 4 pixels
        int m    = t / (1048576 / 4);
        int pix4 = t - m * (1048576 / 4);
        const float4* c0p = (const float4*)(PAF + ((size_t)(2 * m)     << 20));
        const float4* c1p = (const float4*)(PAF + ((size_t)(2 * m + 1) << 20));
        float4 c0 = __ldg(&c0p[pix4]);
        float4 c1 = __ldg(&c1p[pix4]);
        __half2 h0 = __floats2half2_rn(c0.x, c1.x);
        __half2 h1 = __floats2half2_rn(c0.y, c1.y);
        __half2 h2 = __floats2half2_rn(c0.z, c1.z);
        __half2 h3 = __floats2half2_rn(c0.w, c1.w);
        uint4 pk;
        pk.x = *(unsigned*)&h0; pk.y = *(unsigned*)&h1;
        pk.z = *(unsigned*)&h2; pk.w = *(unsigned*)&h3;
        ((uint4*)(g_paf + ((size_t)m << 20)))[pix4] = pk;
    } else {
        int i = (blockIdx.x - REPACK_BLOCKS) * 256 + threadIdx.x;   // < NPTS
        int s = i / KPTS;
        int x = __ldg(&sk[3 * i + 1]);
        int y = __ldg(&sk[3 * i + 2]);
        int pix = (y << 10) + x;                   // row = coord1, col = coord0
        float ax = 0.f, ay = 0.f, bx = 0.f, by = 0.f;
        if (s < NMAPS) {                           // point used as p1 on map s
            ax = __ldg(&PAF[((size_t)(2 * s)     << 20) + pix]);
            ay = __ldg(&PAF[((size_t)(2 * s + 1) << 20) + pix]);
        }
        if (s >= 1) {                              // point used as p2 on map s-1
            int m = s - 1;
            bx = __ldg(&PAF[((size_t)(2 * m)     << 20) + pix]);
            by = __ldg(&PAF[((size_t)(2 * m + 1) << 20) + pix]);
        }
        g_ptA[i] = make_int4(x, y, __float_as_int(ax), __float_as_int(ay));
        g_ptB[i] = make_int4(x, y, __float_as_int(bx), __float_as_int(by));
    }
}

// 2 edges per thread: (a0, b) and (a0+1, b) share p1 -> one P1 load, 16 gathers in flight.
__global__ __launch_bounds__(256) void paf_main_kernel(float* __restrict__ out) {
    int t   = blockIdx.x;
    int m   = t / (APAIRS * 3);
    int rem = t - m * (APAIRS * 3);
    int ap  = rem / 3;
    int b   = (rem - ap * 3) * 256 + threadIdx.x;
    int a0  = ap * 2;

    int i1 = m * KPTS + b;
    int4 P1  = __ldg(&g_ptA[i1]);
    int4 P2a = __ldg(&g_ptB[(m + 1) * KPTS + a0]);
    int4 P2b = __ldg(&g_ptB[(m + 1) * KPTS + a0 + 1]);

    int p1x = P1.x, p1y = P1.y;
    int dxa = P2a.x - p1x, dya = P2a.y - p1y;
    int dxb = P2b.x - p1x, dyb = P2b.y - p1y;

    const __half2* paf = g_paf + ((size_t)m << 20);

    // Interior samples x=1..8: pos = (p1*(9-x) + p2*x) // 9
    // n in [0, 9207]; floor(n/9) == (n*58255)>>19 exactly on that range.
    __half2 va[8], vb[8];
    int nxa = p1x * 9, nya = p1y * 9;
    int nxb = nxa,     nyb = nya;
#pragma unroll
    for (int s = 0; s < 8; s++) {
        nxa += dxa; nya += dya;
        int lxa = (nxa * 58255) >> 19;
        int lya = (nya * 58255) >> 19;
        va[s] = __ldg(&paf[(lya << 10) + lxa]);
        nxb += dxb; nyb += dyb;
        int lxb = (nxb * 58255) >> 19;
        int lyb = (nyb * 58255) >> 19;
        vb[s] = __ldg(&paf[(lyb << 10) + lxb]);
    }

    float p1sx = __int_as_float(P1.z), p1sy = __int_as_float(P1.w);

    // Edge A
    float fdx = (float)dxa, fdy = (float)dya;
    float Ra = sqrtf(fdx * fdx + fdy * fdy);
    float sx = p1sx + __int_as_float(P2a.z);
    float sy = p1sy + __int_as_float(P2a.w);
#pragma unroll
    for (int s = 0; s < 8; s++) {
        float2 f = __half22float2(va[s]);
        sx += f.x; sy += f.y;
    }
    float acc = fdx * sx + fdy * sy;
    float lia = (Ra > 0.f) ? (acc / (10.f * Ra)) : 0.f;   // NaN (R==0) -> 0

    // Edge B
    fdx = (float)dxb; fdy = (float)dyb;
    float Rb = sqrtf(fdx * fdx + fdy * fdy);
    sx = p1sx + __int_as_float(P2b.z);
    sy = p1sy + __int_as_float(P2b.w);
#pragma unroll
    for (int s = 0; s < 8; s++) {
        float2 f = __half22float2(vb[s]);
        sx += f.x; sy += f.y;
    }
    acc = fdx * sx + fdy * sy;
    float lib = (Rb > 0.f) ? (acc / (10.f * Rb)) : 0.f;

    // Output layout (float32): rows [i1 | i2 | li | R], each ETOT long
    int idxa = m * EPM + a0 * KPTS + b;
    int idxb = idxa + KPTS;
    float fi1 = (float)i1;
    int i2a = (m + 1) * KPTS + a0;
    out[idxa]            = fi1;
    out[idxb]            = fi1;
    out[ETOT + idxa]     = (float)i2a;
    out[ETOT + idxb]     = (float)(i2a + 1);
    out[2 * ETOT + idxa] = lia;
    out[2 * ETOT + idxb] = lib;
    out[3 * ETOT + idxa] = Ra;
    out[3 * ETOT + idxb] = Rb;
}

extern "C" void kernel_launch(void* const* d_in, const int* in_sizes, int n_in,
                              void* d_out, int out_size) {
    const int*   sk  = (const int*)d_in[0];     // skeletons: (6144, 3) int32 [seg, x, y]
    const float* PAF = (const float*)d_in[1];   // (7, 2, 1024, 1024) float32
    float* out = (float*)d_out;

    // Maximize L1D carveout for the gather kernel (it uses no shared memory).
    cudaFuncSetAttribute(paf_main_kernel,
                         cudaFuncAttributePreferredSharedMemoryCarveout, 0);

    prep_kernel<<<REPACK_BLOCKS + TABLE_BLOCKS, 256>>>(sk, PAF);
    paf_main_kernel<<<MAIN_BLOCKS, 256>>>(out);
}